// round 16
// baseline (speedup 1.0000x reference)
#include <cuda_runtime.h>
#include <math.h>
#include <stdint.h>

#define DIM    64
#define NCODES 1024
#define NROWS  65536
#define HW     4096
#define QELEMS 4194304
#define FULL_OUT 71368706

__device__ float  g_b[NCODES];
__device__ int    g_hist[NCODES];
__device__ double g_loss;

// ---------------------------------------------------------------------------
// init: hist/loss zero + b_k = ||e_k||^2 with the reference rounding chain.
// ---------------------------------------------------------------------------
__global__ void init_kernel(const float* __restrict__ emb) {
    int t = blockIdx.x * 128 + threadIdx.x;        // code 0..1023
    g_hist[t] = 0;
    if (t == 0) g_loss = 0.0;
    const float4* e4 = (const float4*)(emb + t * DIM);
    float4 v[16];
#pragma unroll
    for (int i = 0; i < 16; ++i) v[i] = e4[i];
    float s = 0.f;
#pragma unroll
    for (int i = 0; i < 16; ++i) {
        s = __fadd_rn(s, __fmul_rn(v[i].x, v[i].x));
        s = __fadd_rn(s, __fmul_rn(v[i].y, v[i].y));
        s = __fadd_rn(s, __fmul_rn(v[i].z, v[i].z));
        s = __fadd_rn(s, __fmul_rn(v[i].w, v[i].w));
    }
    g_b[t] = s;
}

// ---------------------------------------------------------------------------
// fused exact argmin, 64-row tiles. Thread tile: 2 rows (tr, tr+32) x 8 codes.
// Encodings zero-stores are streamed through the 16 chunks (hidden in FFMA
// issue gaps); only the per-row 1.0 lands in the epilogue.
// ---------------------------------------------------------------------------
__global__ void __launch_bounds__(256, 3) vq_kernel(
    const float* __restrict__ xin, const float* __restrict__ emb,
    float* __restrict__ oq, float* __restrict__ oenc, float* __restrict__ oidx)
{
    __shared__ __align__(16) float Xs[DIM * 64];    // 16 KB fp32 [d][row]
    __shared__ __align__(16) float Es[64 * DIM];    // 16 KB one E chunk [code][d]
    __shared__ unsigned long long keys[64];
    __shared__ int sidx[64];

    int tid = threadIdx.x;
    int tr  = tid & 31;               // rows tr and tr+32
    int tc  = tid >> 5;               // codes tc*8 .. tc*8+7 per chunk (warp-uniform)
    int n0  = blockIdx.x * 64;
    int img = n0 >> 12, hw0 = n0 & 4095;
    const float* gbase = xin + (size_t)img * (DIM * HW) + hw0;

    // stage X tile: NCHW -> smem[d][row], coalesced 256B runs
    for (int i = tid; i < DIM * 64; i += 256) {
        int d = i >> 6, r = i & 63;
        Xs[i] = gbase[d * HW + r];
    }
    if (tid < 64) keys[tid] = 0xFFFFFFFFFFFFFFFFull;
    __syncthreads();

    // exact a per row (reference chain: sequential d, round-mul then round-add)
    int r0 = tr, r1 = tr + 32;
    float a0 = 0.f, a1 = 0.f;
#pragma unroll
    for (int d = 0; d < DIM; ++d) {
        float v0 = Xs[d * 64 + r0], v1 = Xs[d * 64 + r1];
        a0 = __fadd_rn(a0, __fmul_rn(v0, v0));
        a1 = __fadd_rn(a1, __fmul_rn(v1, v1));
    }

    const float INF = __int_as_float(0x7f800000);
    float best0 = INF, best1 = INF;
    int   bix0 = 0, bix1 = 0;

    float2* enc2 = oenc ? (float2*)oenc : nullptr;
    const float2 z2 = make_float2(0.f, 0.f);

    for (int c = 0; c < 16; ++c) {
        // stage E chunk (64 codes x 64 dims fp32)
        {
            const float4* src = (const float4*)(emb + c * (64 * DIM));
            float4* dst = (float4*)Es;
#pragma unroll
            for (int k = 0; k < 4; ++k) dst[tid + k * 256] = src[tid + k * 256];
        }
        // streamed encodings zero-stores: rows n0..n0+63, cols c*64..c*64+63
        if (enc2) {
#pragma unroll
            for (int k = 0; k < 8; ++k) {
                int i = tid + k * 256;             // 0..2047 float2 slots
                int row = i >> 5, cp = i & 31;     // 32 float2 = 64 cols
                enc2[(size_t)(n0 + row) * 512 + c * 32 + cp] = z2;
            }
        }
        __syncthreads();

        float acc0[8], acc1[8];
#pragma unroll
        for (int j = 0; j < 8; ++j) { acc0[j] = 0.f; acc1[j] = 0.f; }

#pragma unroll 4
        for (int dk = 0; dk < DIM; dk += 4) {
            float4 e4[8];
#pragma unroll
            for (int j = 0; j < 8; ++j)           // warp-uniform -> broadcast
                e4[j] = *(const float4*)&Es[(tc * 8 + j) * DIM + dk];
#pragma unroll
            for (int t = 0; t < 4; ++t) {
                float x0 = Xs[(dk + t) * 64 + r0];  // lane=row: conflict-free
                float x1 = Xs[(dk + t) * 64 + r1];
#pragma unroll
                for (int j = 0; j < 8; ++j) {
                    float ev = ((const float*)&e4[j])[t];
                    acc0[j] = __fmaf_rn(x0, ev, acc0[j]);
                    acc1[j] = __fmaf_rn(x1, ev, acc1[j]);
                }
            }
        }

        // score s = round((a+b) - 2m): fma(-2, m, ab) == fadd(fadd(a,b), -2m)
        // (-2m exact, single rounding either way). Strict < + ascending codes
        // == first-occurrence argmin.
#pragma unroll
        for (int j = 0; j < 8; ++j) {
            int code = c * 64 + tc * 8 + j;
            float bb = __ldg(&g_b[code]);
            float s0 = __fmaf_rn(-2.0f, acc0[j], __fadd_rn(a0, bb));
            float s1 = __fmaf_rn(-2.0f, acc1[j], __fadd_rn(a1, bb));
            if (s0 < best0) { best0 = s0; bix0 = code; }
            if (s1 < best1) { best1 = s1; bix1 = code; }
        }
        __syncthreads();                           // Es reads done before restage
    }

    // cross-thread row argmin: packed (score_bits<<32)|code, atomicMin.
    // Scores >0 -> fp32 bits order-preserving; ties -> smaller code wins.
    atomicMin(&keys[r0], ((unsigned long long)__float_as_uint(best0) << 32) | (unsigned)bix0);
    atomicMin(&keys[r1], ((unsigned long long)__float_as_uint(best1) << 32) | (unsigned)bix1);
    __syncthreads();

    double lsum = 0.0;
    if (tid < 64) {
        int idx = (int)(keys[tid] & 0xFFFFFFFFull);
        sidx[tid] = idx;
        atomicAdd(&g_hist[idx], 1);
        if (oidx) oidx[n0 + tid] = (float)idx;
        const float* e = emb + idx * DIM;
        float ls = 0.f;
#pragma unroll
        for (int d = 0; d < DIM; ++d) {
            float dif = e[d] - Xs[d * 64 + tid];
            ls = __fmaf_rn(dif, dif, ls);
        }
        lsum = (double)ls;
    }
#pragma unroll
    for (int off = 16; off; off >>= 1)
        lsum += __shfl_down_sync(0xffffffffu, lsum, off);
    if (tid < 64 && (tid & 31) == 0) atomicAdd(&g_loss, lsum);
    __syncthreads();

    // quantized_st, NCHW: 64-float (256B) coalesced runs per channel
    for (int i = tid; i < DIM * 64; i += 256) {
        int cc = i >> 6, row = i & 63;
        oq[(size_t)img * (DIM * HW) + cc * HW + hw0 + row] = emb[sidx[row] * DIM + cc];
    }

    // the single 1.0 per row (zeros already streamed during the mainloop;
    // ordering guaranteed by the __syncthreads() between the stores)
    if (oenc && tid < 64)
        oenc[(size_t)(n0 + tid) * NCODES + sidx[tid]] = 1.0f;
}

// ---------------------------------------------------------------------------
__global__ void finalize_kernel(float* __restrict__ oloss, float* __restrict__ operp) {
    int t = threadIdx.x;                           // 1024 threads
    double p = (double)g_hist[t] / 65536.0;
    double h = -p * log(p + 1e-10);
    __shared__ double sh[32];
#pragma unroll
    for (int off = 16; off; off >>= 1) h += __shfl_down_sync(0xffffffffu, h, off);
    if ((t & 31) == 0) sh[t >> 5] = h;
    __syncthreads();
    if (t < 32) {
        double v = sh[t];
#pragma unroll
        for (int off = 16; off; off >>= 1) v += __shfl_down_sync(0xffffffffu, v, off);
        if (t == 0) {
            operp[0] = (float)exp(v);
            oloss[0] = (float)(1.25 * (g_loss / (double)QELEMS));
        }
    }
}

// ---------------------------------------------------------------------------
extern "C" void kernel_launch(void* const* d_in, const int* in_sizes, int n_in,
                              void* d_out, int out_size) {
    const float* xin = (const float*)d_in[0];
    const float* emb = (const float*)d_in[1];
    if (n_in >= 2 && in_sizes[0] == NCODES * DIM && in_sizes[1] == QELEMS) {
        xin = (const float*)d_in[1];
        emb = (const float*)d_in[0];
    }
    float* out  = (float*)d_out;
    bool   full = (out_size >= FULL_OUT);
    float* o_q   = full ? out + 1 : out;
    float* o_enc = full ? out + (size_t)QELEMS + 2 : nullptr;
    float* o_idx = full ? out + (size_t)QELEMS + 2 + (size_t)NROWS * NCODES : nullptr;

    init_kernel<<<8, 128>>>(emb);
    vq_kernel<<<1024, 256>>>(xin, emb, o_q, o_enc, o_idx);
    if (full) finalize_kernel<<<1, 1024>>>(out, out + QELEMS + 1);
}

// round 17
// speedup vs baseline: 1.2723x; 1.2723x over previous
#include <cuda_runtime.h>
#include <math.h>
#include <stdint.h>

#define DIM    64
#define NCODES 1024
#define NROWS  65536
#define HW     4096
#define QELEMS 4194304
#define FULL_OUT 71368706

__device__ float  g_b[NCODES];
__device__ int    g_hist[NCODES];
__device__ double g_loss;

// ---------------------------------------------------------------------------
// init: hist/loss zero + b_k = ||e_k||^2 with the reference rounding chain.
// ---------------------------------------------------------------------------
__global__ void init_kernel(const float* __restrict__ emb) {
    int t = blockIdx.x * 128 + threadIdx.x;        // code 0..1023
    g_hist[t] = 0;
    if (t == 0) g_loss = 0.0;
    const float4* e4 = (const float4*)(emb + t * DIM);
    float4 v[16];
#pragma unroll
    for (int i = 0; i < 16; ++i) v[i] = e4[i];
    float s = 0.f;
#pragma unroll
    for (int i = 0; i < 16; ++i) {
        s = __fadd_rn(s, __fmul_rn(v[i].x, v[i].x));
        s = __fadd_rn(s, __fmul_rn(v[i].y, v[i].y));
        s = __fadd_rn(s, __fmul_rn(v[i].z, v[i].z));
        s = __fadd_rn(s, __fmul_rn(v[i].w, v[i].w));
    }
    g_b[t] = s;
}

// ---------------------------------------------------------------------------
// fused exact argmin, 64-row blocks, 128 threads, 4-rows x 8-codes tile
// (12 LDS per 128 FMA: ~9% LDS issue share vs 25% in the 2x8 tile).
// Encodings zero-stores streamed through the 16 chunks; per-row 1.0 in the
// epilogue. All compared FP chains identical to prior passing kernels.
// ---------------------------------------------------------------------------
__global__ void __launch_bounds__(128, 5) vq_kernel(
    const float* __restrict__ xin, const float* __restrict__ emb,
    float* __restrict__ oq, float* __restrict__ oenc, float* __restrict__ oidx)
{
    __shared__ __align__(16) float Xs[DIM * 64];    // 16 KB fp32 [d][row]
    __shared__ __align__(16) float Es[64 * DIM];    // 16 KB one E chunk [code][d]
    __shared__ float s_a[64];
    __shared__ unsigned long long keys[64];
    __shared__ int sidx[64];

    int tid = threadIdx.x;
    int tr  = tid & 15;               // rows tr*4 .. tr*4+3
    int tc  = tid >> 4;               // codes tc*8 .. tc*8+7 per chunk
    int n0  = blockIdx.x * 64;
    int img = n0 >> 12, hw0 = n0 & 4095;
    const float* gbase = xin + (size_t)img * (DIM * HW) + hw0;

    // stage X tile: NCHW -> smem[d][row], coalesced 256B runs
    for (int i = tid; i < DIM * 64; i += 128) {
        int d = i >> 6, r = i & 63;
        Xs[i] = gbase[d * HW + r];
    }
    if (tid < 64) keys[tid] = 0xFFFFFFFFFFFFFFFFull;
    __syncthreads();

    // exact a per row (reference chain), computed once, shared
    if (tid < 64) {
        float a = 0.f;
#pragma unroll
        for (int d = 0; d < DIM; ++d) {
            float v = Xs[d * 64 + tid];
            a = __fadd_rn(a, __fmul_rn(v, v));
        }
        s_a[tid] = a;
    }
    __syncthreads();

    float a[4];
#pragma unroll
    for (int rs = 0; rs < 4; ++rs) a[rs] = s_a[tr * 4 + rs];

    const float INF = __int_as_float(0x7f800000);
    float best[4];
    int   bidx[4];
#pragma unroll
    for (int rs = 0; rs < 4; ++rs) { best[rs] = INF; bidx[rs] = 0; }

    float2* enc2 = oenc ? (float2*)oenc : nullptr;
    const float2 z2 = make_float2(0.f, 0.f);

    for (int c = 0; c < 16; ++c) {
        // stage E chunk (64 codes x 64 dims fp32)
        {
            const float4* src = (const float4*)(emb + c * (64 * DIM));
            float4* dst = (float4*)Es;
#pragma unroll
            for (int k = 0; k < 8; ++k) dst[tid + k * 128] = src[tid + k * 128];
        }
        // streamed encodings zero-stores: rows n0..+63, cols c*64..+63
        if (enc2) {
#pragma unroll
            for (int k = 0; k < 16; ++k) {
                int i = tid + k * 128;             // 0..2047 float2 slots
                int row = i >> 5, cp = i & 31;     // 32 float2 = 64 cols
                enc2[(size_t)(n0 + row) * 512 + c * 32 + cp] = z2;
            }
        }
        __syncthreads();

        float acc[4][8];
#pragma unroll
        for (int rs = 0; rs < 4; ++rs)
#pragma unroll
            for (int j = 0; j < 8; ++j) acc[rs][j] = 0.f;

        // 12 LDS.128 per 128 FMA (sequential-d chain per (row,code))
#pragma unroll 4
        for (int dk = 0; dk < DIM; dk += 4) {
            float4 e4[8];
#pragma unroll
            for (int j = 0; j < 8; ++j)
                e4[j] = *(const float4*)&Es[(tc * 8 + j) * DIM + dk];
#pragma unroll
            for (int t = 0; t < 4; ++t) {
                float4 xv = *(const float4*)&Xs[(dk + t) * 64 + tr * 4];
#pragma unroll
                for (int j = 0; j < 8; ++j) {
                    float ev = ((const float*)&e4[j])[t];
                    acc[0][j] = __fmaf_rn(xv.x, ev, acc[0][j]);
                    acc[1][j] = __fmaf_rn(xv.y, ev, acc[1][j]);
                    acc[2][j] = __fmaf_rn(xv.z, ev, acc[2][j]);
                    acc[3][j] = __fmaf_rn(xv.w, ev, acc[3][j]);
                }
            }
        }

        // score s = round((a+b) - 2m): fma(-2,m,ab) == fadd(fadd(a,b),-2m).
        // Strict < + ascending codes == first-occurrence argmin.
#pragma unroll
        for (int j = 0; j < 8; ++j) {
            int code = c * 64 + tc * 8 + j;
            float bb = __ldg(&g_b[code]);
#pragma unroll
            for (int rs = 0; rs < 4; ++rs) {
                float s = __fmaf_rn(-2.0f, acc[rs][j], __fadd_rn(a[rs], bb));
                if (s < best[rs]) { best[rs] = s; bidx[rs] = code; }
            }
        }
        __syncthreads();                           // Es reads done before restage
    }

    // cross-thread row argmin: packed (score_bits<<32)|code, atomicMin.
    // Scores >0 -> fp32 bits order-preserving; ties -> smaller code wins.
#pragma unroll
    for (int rs = 0; rs < 4; ++rs)
        atomicMin(&keys[tr * 4 + rs],
                  ((unsigned long long)__float_as_uint(best[rs]) << 32) | (unsigned)bidx[rs]);
    __syncthreads();

    double lsum = 0.0;
    if (tid < 64) {
        int idx = (int)(keys[tid] & 0xFFFFFFFFull);
        sidx[tid] = idx;
        atomicAdd(&g_hist[idx], 1);
        if (oidx) oidx[n0 + tid] = (float)idx;
        const float* e = emb + idx * DIM;
        float ls = 0.f;
#pragma unroll
        for (int d = 0; d < DIM; ++d) {
            float dif = e[d] - Xs[d * 64 + tid];
            ls = __fmaf_rn(dif, dif, ls);
        }
        lsum = (double)ls;
    }
#pragma unroll
    for (int off = 16; off; off >>= 1)
        lsum += __shfl_down_sync(0xffffffffu, lsum, off);
    if (tid < 64 && (tid & 31) == 0) atomicAdd(&g_loss, lsum);
    __syncthreads();

    // quantized_st, NCHW: 64-float (256B) coalesced runs per channel
    for (int i = tid; i < DIM * 64; i += 128) {
        int cc = i >> 6, row = i & 63;
        oq[(size_t)img * (DIM * HW) + cc * HW + hw0 + row] = emb[sidx[row] * DIM + cc];
    }

    // the single 1.0 per row (zeros already streamed during the mainloop;
    // ordering guaranteed by the __syncthreads() between the stores)
    if (oenc && tid < 64)
        oenc[(size_t)(n0 + tid) * NCODES + sidx[tid]] = 1.0f;
}

// ---------------------------------------------------------------------------
__global__ void finalize_kernel(float* __restrict__ oloss, float* __restrict__ operp) {
    int t = threadIdx.x;                           // 1024 threads
    double p = (double)g_hist[t] / 65536.0;
    double h = -p * log(p + 1e-10);
    __shared__ double sh[32];
#pragma unroll
    for (int off = 16; off; off >>= 1) h += __shfl_down_sync(0xffffffffu, h, off);
    if ((t & 31) == 0) sh[t >> 5] = h;
    __syncthreads();
    if (t < 32) {
        double v = sh[t];
#pragma unroll
        for (int off = 16; off; off >>= 1) v += __shfl_down_sync(0xffffffffu, v, off);
        if (t == 0) {
            operp[0] = (float)exp(v);
            oloss[0] = (float)(1.25 * (g_loss / (double)QELEMS));
        }
    }
}

// ---------------------------------------------------------------------------
extern "C" void kernel_launch(void* const* d_in, const int* in_sizes, int n_in,
                              void* d_out, int out_size) {
    const float* xin = (const float*)d_in[0];
    const float* emb = (const float*)d_in[1];
    if (n_in >= 2 && in_sizes[0] == NCODES * DIM && in_sizes[1] == QELEMS) {
        xin = (const float*)d_in[1];
        emb = (const float*)d_in[0];
    }
    float* out  = (float*)d_out;
    bool   full = (out_size >= FULL_OUT);
    float* o_q   = full ? out + 1 : out;
    float* o_enc = full ? out + (size_t)QELEMS + 2 : nullptr;
    float* o_idx = full ? out + (size_t)QELEMS + 2 + (size_t)NROWS * NCODES : nullptr;

    init_kernel<<<8, 128>>>(emb);
    vq_kernel<<<1024, 128>>>(xin, emb, o_q, o_enc, o_idx);
    if (full) finalize_kernel<<<1, 1024>>>(out, out + QELEMS + 1);
}